// round 4
// baseline (speedup 1.0000x reference)
#include <cuda_runtime.h>
#include <math.h>

#define BATCH 256
#define TT    64
#define NN    128
#define HH    512
#define KDIM  640    // NN + HH
#define GDIM  2048   // 4*HH

// ---------------- device scratch (no allocations allowed) ----------------
__device__ float g_z2[TT * BATCH * NN];     // 8 MB   z2[s][b][n]  (s-major for coalesced streaming)
__device__ float g_z1[BATCH * TT];          // per-step z1
__device__ float g_A[2][BATCH * KDIM];      // double-buffered GEMM A: [wx(128) | h(512)]
__device__ float g_c[BATCH * HH];           // LSTM cell state
__device__ float g_Wt[KDIM * GDIM];         // transposed, gate-interleaved [Wih|Whh]
__device__ float g_bias[GDIM];              // gate-interleaved b_ih + b_hh

__device__ __forceinline__ float fsigmoid(float x) {
    return 1.0f / (1.0f + expf(-x));
}
__device__ __forceinline__ float ftanh(float x) {
    float ax = fabsf(x);
    float e2 = expf(-2.0f * ax);
    float r = (1.0f - e2) / (1.0f + e2);
    return copysignf(r, x);
}
__device__ __forceinline__ float ftanh_fast(float x) {
    float y;
    asm("tanh.approx.f32 %0, %1;" : "=f"(y) : "f"(x));
    return y;
}

// ---------------- init: zero recurrent state ----------------
__global__ void k_init() {
    int idx = blockIdx.x * blockDim.x + threadIdx.x;
    int totA = 2 * BATCH * KDIM;
    int totC = BATCH * HH;
    if (idx < totA) ((float*)g_A)[idx] = 0.0f;
    else if (idx < totA + totC) g_c[idx - totA] = 0.0f;
}

// ---------------- precompute: gate-interleaved transposed weights ----------------
__global__ void k_prep_w(const float* __restrict__ Wih, const float* __restrict__ Whh,
                         const float* __restrict__ bih, const float* __restrict__ bhh) {
    int idx = blockIdx.x * blockDim.x + threadIdx.x;
    if (idx < KDIM * GDIM) {
        int kk = idx / GDIM;
        int j  = idx % GDIM;
        int k = j >> 2, g = j & 3;
        int row = g * HH + k;
        float v = (kk < NN) ? Wih[row * NN + kk] : Whh[row * HH + (kk - NN)];
        g_Wt[idx] = v;
    }
    if (idx < GDIM) {
        int k = idx >> 2, g = idx & 3;
        g_bias[idx] = bih[g * HH + k] + bhh[g * HH + k];
    }
}

// ---------------- precompute: z2[s][b][n] = sum_t dx[b][t][n]*Wa2[s][t] + ba2[s] ----------------
__global__ void k_z2(const float* __restrict__ dx, const float* __restrict__ Wa2,
                     const float* __restrict__ ba2) {
    __shared__ float dxs[TT][NN];     // 32 KB
    __shared__ float wa2s[TT][TT];    // 16 KB
    int b = blockIdx.x;
    int tid = threadIdx.x;            // 128 threads
    for (int i = tid; i < TT * NN; i += 128) dxs[i / NN][i % NN] = dx[b * TT * NN + i];
    for (int i = tid; i < TT * TT; i += 128) wa2s[i / TT][i % TT] = Wa2[i];
    __syncthreads();
    int n = tid;
    for (int s0 = 0; s0 < TT; s0 += 8) {
        float acc[8];
        #pragma unroll
        for (int u = 0; u < 8; u++) acc[u] = ba2[s0 + u];
        for (int t = 0; t < TT; t++) {
            float d = dxs[t][n];
            #pragma unroll
            for (int u = 0; u < 8; u++) acc[u] += d * wa2s[s0 + u][t];
        }
        #pragma unroll
        for (int u = 0; u < 8; u++)
            g_z2[(s0 + u) * (BATCH * NN) + b * NN + n] = acc[u];
    }
}

// ---------------- per-step kernel Z1: z1[b][s] = [h|c] . Wa1[s] + ba1[s] ----------------
// grid 32 blocks x 256 threads; warp-per-batch, hs register-resident
__global__ void k_z1(const float* __restrict__ Wa1, const float* __restrict__ ba1, int cur) {
    int warp = threadIdx.x >> 5, lane = threadIdx.x & 31;
    int b = blockIdx.x * 8 + warp;
    const float* Acur = g_A[cur];
    float hreg[32];
    #pragma unroll
    for (int u = 0; u < 16; u++) hreg[u]      = Acur[b * KDIM + NN + u * 32 + lane];
    #pragma unroll
    for (int u = 0; u < 16; u++) hreg[16 + u] = g_c[b * HH + u * 32 + lane];
    for (int s = 0; s < TT; s++) {
        const float* wrow = Wa1 + s * 1024;
        float a = 0.0f;
        #pragma unroll
        for (int u = 0; u < 32; u++) a += wrow[u * 32 + lane] * hreg[u];
        #pragma unroll
        for (int o = 16; o > 0; o >>= 1) a += __shfl_xor_sync(0xffffffffu, a, o);
        if (lane == 0) g_z1[b * TT + s] = a + ba1[s];
    }
}

// ---------------- per-step kernel A: attention + softmax + wx ----------------
// grid 128 blocks (2 batches each), 256 threads; streams z2[s][b][n] coalesced
__global__ void k_attn(const float* __restrict__ dx, const float* __restrict__ Wa3,
                       const float* __restrict__ ba3, int t, int cur) {
    __shared__ float z1s[2][TT];
    __shared__ float wa3s[TT];
    __shared__ float redm[8], reds[8];
    int b0 = blockIdx.x * 2;
    int tid = threadIdx.x;
    if (tid < 128) z1s[tid >> 6][tid & 63] = g_z1[(b0 + (tid >> 6)) * TT + (tid & 63)];
    if (tid < TT)  wa3s[tid] = Wa3[tid];
    __syncthreads();

    int q = tid >> 7, n = tid & 127;
    int b = b0 + q;
    int warp = tid >> 5, lane = tid & 31;
    float e = ba3[0];
    const float* z2p = g_z2 + b * NN + n;
    #pragma unroll 8
    for (int s = 0; s < TT; s++) {
        float v = z2p[s * (BATCH * NN)];
        e += ftanh_fast(z1s[q][s] + v) * wa3s[s];
    }
    // softmax over n within each q-group (warps q*4 .. q*4+3)
    float m = e;
    #pragma unroll
    for (int o = 16; o > 0; o >>= 1) m = fmaxf(m, __shfl_xor_sync(0xffffffffu, m, o));
    if (lane == 0) redm[warp] = m;
    __syncthreads();
    float gm = fmaxf(fmaxf(redm[q * 4 + 0], redm[q * 4 + 1]),
                     fmaxf(redm[q * 4 + 2], redm[q * 4 + 3]));
    float ex = expf(e - gm);
    float ssum = ex;
    #pragma unroll
    for (int o = 16; o > 0; o >>= 1) ssum += __shfl_xor_sync(0xffffffffu, ssum, o);
    if (lane == 0) reds[warp] = ssum;
    __syncthreads();
    float gs = reds[q * 4 + 0] + reds[q * 4 + 1] + reds[q * 4 + 2] + reds[q * 4 + 3];
    float w = ex / gs;
    g_A[cur][b * KDIM + n] = w * dx[(b * TT + t) * NN + n];
}

// ---------------- per-step kernel B: gates GEMM + fused LSTM epilogue ----------------
__global__ void k_lstm(float* __restrict__ out, int t, int cur) {
    __shared__ float As[16][68];
    __shared__ float Bs[16][68];
    __shared__ float gbuf[64][65];
    int tid = threadIdx.x;
    int bx = blockIdx.x;
    int by = blockIdx.y;
    int b0 = by * 64;
    int j0 = bx * 64;
    const float* Acur = g_A[cur];
    int tx = tid & 15, ty = tid >> 4;
    int lr = tid >> 2;
    int lc = (tid & 3) * 4;
    int bkk = tid >> 4;
    int bjc = (tid & 15) * 4;
    float acc[4][4] = {};

    for (int k0 = 0; k0 < KDIM; k0 += 16) {
        float4 av = *(const float4*)(Acur + (b0 + lr) * KDIM + k0 + lc);
        float4 bv = *(const float4*)(g_Wt + (k0 + bkk) * GDIM + j0 + bjc);
        __syncthreads();
        As[lc + 0][lr] = av.x;
        As[lc + 1][lr] = av.y;
        As[lc + 2][lr] = av.z;
        As[lc + 3][lr] = av.w;
        *(float4*)&Bs[bkk][bjc] = bv;
        __syncthreads();
        #pragma unroll
        for (int k = 0; k < 16; k++) {
            float4 a = *(const float4*)&As[k][ty * 4];
            float4 b = *(const float4*)&Bs[k][tx * 4];
            acc[0][0] += a.x * b.x; acc[0][1] += a.x * b.y; acc[0][2] += a.x * b.z; acc[0][3] += a.x * b.w;
            acc[1][0] += a.y * b.x; acc[1][1] += a.y * b.y; acc[1][2] += a.y * b.z; acc[1][3] += a.y * b.w;
            acc[2][0] += a.z * b.x; acc[2][1] += a.z * b.y; acc[2][2] += a.z * b.z; acc[2][3] += a.z * b.w;
            acc[3][0] += a.w * b.x; acc[3][1] += a.w * b.y; acc[3][2] += a.w * b.z; acc[3][3] += a.w * b.w;
        }
    }
    __syncthreads();
    #pragma unroll
    for (int i = 0; i < 4; i++)
        #pragma unroll
        for (int jj = 0; jj < 4; jj++)
            gbuf[ty * 4 + i][tx * 4 + jj] = acc[i][jj] + g_bias[j0 + tx * 4 + jj];
    __syncthreads();

    float* Anext = g_A[cur ^ 1];
    #pragma unroll
    for (int p = 0; p < 4; p++) {
        int pid = tid * 4 + p;
        int bl = pid >> 4;
        int kl = pid & 15;
        int b = b0 + bl;
        int k = (bx << 4) + kl;
        float gi = gbuf[bl][kl * 4 + 0];
        float gf = gbuf[bl][kl * 4 + 1];
        float gg = gbuf[bl][kl * 4 + 2];
        float go = gbuf[bl][kl * 4 + 3];
        float co = g_c[b * HH + k];
        float cn = fsigmoid(gf) * co + fsigmoid(gi) * ftanh(gg);
        float hn = fsigmoid(go) * ftanh(cn);
        g_c[b * HH + k] = cn;
        Anext[b * KDIM + NN + k] = hn;
        out[(b * TT + t) * HH + k] = hn;
    }
}

// ---------------- launch ----------------
extern "C" void kernel_launch(void* const* d_in, const int* in_sizes, int n_in,
                              void* d_out, int out_size) {
    const float* dx   = (const float*)d_in[0];
    const float* Wa1  = (const float*)d_in[1];
    const float* ba1  = (const float*)d_in[2];
    const float* Wa2  = (const float*)d_in[3];
    const float* ba2  = (const float*)d_in[4];
    const float* Wa3  = (const float*)d_in[5];
    const float* ba3  = (const float*)d_in[6];
    const float* Wih  = (const float*)d_in[7];
    const float* Whh  = (const float*)d_in[8];
    const float* bih  = (const float*)d_in[9];
    const float* bhh  = (const float*)d_in[10];
    float* out = (float*)d_out;

    {
        int tot = 2 * BATCH * KDIM + BATCH * HH;
        k_init<<<(tot + 255) / 256, 256>>>();
    }
    k_prep_w<<<(KDIM * GDIM + 255) / 256, 256>>>(Wih, Whh, bih, bhh);
    k_z2<<<BATCH, 128>>>(dx, Wa2, ba2);

    for (int t = 0; t < TT; t++) {
        int cur = t & 1;
        k_z1<<<BATCH / 8, 256>>>(Wa1, ba1, cur);
        k_attn<<<BATCH / 2, 256>>>(dx, Wa3, ba3, t, cur);
        k_lstm<<<dim3(GDIM / 64, BATCH / 64), 256>>>(out, t, cur);
    }
}

// round 5
// speedup vs baseline: 2.3269x; 2.3269x over previous
#include <cuda_runtime.h>
#include <math.h>

#define BATCH 256
#define TT    64
#define NN    128
#define HH    512
#define KDIM  640    // NN + HH
#define GDIM  2048   // 4*HH

// ---------------- device scratch (no allocations allowed) ----------------
__device__ float g_z2[TT * BATCH * NN];     // 8 MB   z2[s][b][n]  (s-major, coalesced streaming)
__device__ float g_A[2][BATCH * KDIM];      // double-buffered GEMM A: [wx(128) | h(512)]
__device__ float g_c[BATCH * HH];           // LSTM cell state
__device__ float g_Wt[KDIM * GDIM];         // transposed, gate-interleaved [Wih|Whh]
__device__ float g_bias[GDIM];              // gate-interleaved b_ih + b_hh

__device__ __forceinline__ float fsigmoid(float x) {
    return 1.0f / (1.0f + expf(-x));
}
__device__ __forceinline__ float ftanh(float x) {
    float ax = fabsf(x);
    float e2 = expf(-2.0f * ax);
    float r = (1.0f - e2) / (1.0f + e2);
    return copysignf(r, x);
}
__device__ __forceinline__ float ftanh_fast(float x) {
    float y;
    asm("tanh.approx.f32 %0, %1;" : "=f"(y) : "f"(x));
    return y;
}

// ---------------- init: zero recurrent state ----------------
__global__ void k_init() {
    int idx = blockIdx.x * blockDim.x + threadIdx.x;
    int totA = 2 * BATCH * KDIM;
    int totC = BATCH * HH;
    if (idx < totA) ((float*)g_A)[idx] = 0.0f;
    else if (idx < totA + totC) g_c[idx - totA] = 0.0f;
}

// ---------------- precompute: gate-interleaved transposed weights ----------------
__global__ void k_prep_w(const float* __restrict__ Wih, const float* __restrict__ Whh,
                         const float* __restrict__ bih, const float* __restrict__ bhh) {
    int idx = blockIdx.x * blockDim.x + threadIdx.x;
    if (idx < KDIM * GDIM) {
        int kk = idx / GDIM;
        int j  = idx % GDIM;
        int k = j >> 2, g = j & 3;
        int row = g * HH + k;
        float v = (kk < NN) ? Wih[row * NN + kk] : Whh[row * HH + (kk - NN)];
        g_Wt[idx] = v;
    }
    if (idx < GDIM) {
        int k = idx >> 2, g = idx & 3;
        g_bias[idx] = bih[g * HH + k] + bhh[g * HH + k];
    }
}

// ---------------- precompute: z2[s][b][n] = sum_t dx[b][t][n]*Wa2[s][t] + ba2[s] ----------------
__global__ void k_z2(const float* __restrict__ dx, const float* __restrict__ Wa2,
                     const float* __restrict__ ba2) {
    __shared__ float dxs[TT][NN];     // 32 KB
    __shared__ float wa2s[TT][TT];    // 16 KB
    int b = blockIdx.x;
    int tid = threadIdx.x;            // 128 threads
    for (int i = tid; i < TT * NN; i += 128) dxs[i / NN][i % NN] = dx[b * TT * NN + i];
    for (int i = tid; i < TT * TT; i += 128) wa2s[i / TT][i % TT] = Wa2[i];
    __syncthreads();
    int n = tid;
    for (int s0 = 0; s0 < TT; s0 += 8) {
        float acc[8];
        #pragma unroll
        for (int u = 0; u < 8; u++) acc[u] = ba2[s0 + u];
        for (int t = 0; t < TT; t++) {
            float d = dxs[t][n];
            #pragma unroll
            for (int u = 0; u < 8; u++) acc[u] += d * wa2s[s0 + u][t];
        }
        #pragma unroll
        for (int u = 0; u < 8; u++)
            g_z2[(s0 + u) * (BATCH * NN) + b * NN + n] = acc[u];
    }
}

// ---------------- per-step kernel A: z1 GEMV + attention + softmax + wx ----------------
// grid 128 blocks (2 batches each), 256 threads
// z1 computed in-block over smem-resident hs (R1-proven structure);
// attention streams z2[s][b][n] coalesced with tanh.approx.
__global__ void k_attn(const float* __restrict__ dx, const float* __restrict__ Wa1,
                       const float* __restrict__ ba1, const float* __restrict__ Wa3,
                       const float* __restrict__ ba3, int t, int cur) {
    __shared__ float hs[2][1024];
    __shared__ float z1s[2][TT];
    __shared__ float wa3s[TT];
    __shared__ float redm[8], reds[8];
    int b0 = blockIdx.x * 2;
    int tid = threadIdx.x;
    const float* Acur = g_A[cur];
    for (int i = tid; i < 2048; i += 256) {
        int qq = i >> 10, j = i & 1023;
        hs[qq][j] = (j < HH) ? Acur[(b0 + qq) * KDIM + NN + j]
                             : g_c[(b0 + qq) * HH + (j - HH)];
    }
    if (tid < TT) wa3s[tid] = Wa3[tid];
    __syncthreads();

    int warp = tid >> 5, lane = tid & 31;
    for (int s = warp; s < TT; s += 8) {
        float a0 = 0.0f, a1 = 0.0f;
        const float* wrow = Wa1 + s * 1024;
        for (int j = lane; j < 1024; j += 32) {
            float wv = wrow[j];
            a0 += wv * hs[0][j];
            a1 += wv * hs[1][j];
        }
        #pragma unroll
        for (int o = 16; o > 0; o >>= 1) {
            a0 += __shfl_down_sync(0xffffffffu, a0, o);
            a1 += __shfl_down_sync(0xffffffffu, a1, o);
        }
        if (lane == 0) {
            float bb = ba1[s];
            z1s[0][s] = a0 + bb;
            z1s[1][s] = a1 + bb;
        }
    }
    __syncthreads();

    int q = tid >> 7, n = tid & 127;
    int b = b0 + q;
    float e = ba3[0];
    const float* z2p = g_z2 + b * NN + n;
    #pragma unroll 8
    for (int s = 0; s < TT; s++) {
        float v = z2p[s * (BATCH * NN)];
        e += ftanh_fast(z1s[q][s] + v) * wa3s[s];
    }
    // softmax over n within each q-group (warps q*4 .. q*4+3)
    float m = e;
    #pragma unroll
    for (int o = 16; o > 0; o >>= 1) m = fmaxf(m, __shfl_xor_sync(0xffffffffu, m, o));
    if (lane == 0) redm[warp] = m;
    __syncthreads();
    float gm = fmaxf(fmaxf(redm[q * 4 + 0], redm[q * 4 + 1]),
                     fmaxf(redm[q * 4 + 2], redm[q * 4 + 3]));
    float ex = expf(e - gm);
    float ssum = ex;
    #pragma unroll
    for (int o = 16; o > 0; o >>= 1) ssum += __shfl_xor_sync(0xffffffffu, ssum, o);
    if (lane == 0) reds[warp] = ssum;
    __syncthreads();
    float gs = reds[q * 4 + 0] + reds[q * 4 + 1] + reds[q * 4 + 2] + reds[q * 4 + 3];
    float w = ex / gs;
    g_A[cur][b * KDIM + n] = w * dx[(b * TT + t) * NN + n];
}

// ---------------- per-step kernel B: gates GEMM + fused LSTM epilogue ----------------
__global__ void k_lstm(float* __restrict__ out, int t, int cur) {
    __shared__ float As[16][68];
    __shared__ float Bs[16][68];
    __shared__ float gbuf[64][65];
    int tid = threadIdx.x;
    int bx = blockIdx.x;
    int by = blockIdx.y;
    int b0 = by * 64;
    int j0 = bx * 64;
    const float* Acur = g_A[cur];
    int tx = tid & 15, ty = tid >> 4;
    int lr = tid >> 2;
    int lc = (tid & 3) * 4;
    int bkk = tid >> 4;
    int bjc = (tid & 15) * 4;
    float acc[4][4] = {};

    for (int k0 = 0; k0 < KDIM; k0 += 16) {
        float4 av = *(const float4*)(Acur + (b0 + lr) * KDIM + k0 + lc);
        float4 bv = *(const float4*)(g_Wt + (k0 + bkk) * GDIM + j0 + bjc);
        __syncthreads();
        As[lc + 0][lr] = av.x;
        As[lc + 1][lr] = av.y;
        As[lc + 2][lr] = av.z;
        As[lc + 3][lr] = av.w;
        *(float4*)&Bs[bkk][bjc] = bv;
        __syncthreads();
        #pragma unroll
        for (int k = 0; k < 16; k++) {
            float4 a = *(const float4*)&As[k][ty * 4];
            float4 b = *(const float4*)&Bs[k][tx * 4];
            acc[0][0] += a.x * b.x; acc[0][1] += a.x * b.y; acc[0][2] += a.x * b.z; acc[0][3] += a.x * b.w;
            acc[1][0] += a.y * b.x; acc[1][1] += a.y * b.y; acc[1][2] += a.y * b.z; acc[1][3] += a.y * b.w;
            acc[2][0] += a.z * b.x; acc[2][1] += a.z * b.y; acc[2][2] += a.z * b.z; acc[2][3] += a.z * b.w;
            acc[3][0] += a.w * b.x; acc[3][1] += a.w * b.y; acc[3][2] += a.w * b.z; acc[3][3] += a.w * b.w;
        }
    }
    __syncthreads();
    #pragma unroll
    for (int i = 0; i < 4; i++)
        #pragma unroll
        for (int jj = 0; jj < 4; jj++)
            gbuf[ty * 4 + i][tx * 4 + jj] = acc[i][jj] + g_bias[j0 + tx * 4 + jj];
    __syncthreads();

    float* Anext = g_A[cur ^ 1];
    #pragma unroll
    for (int p = 0; p < 4; p++) {
        int pid = tid * 4 + p;
        int bl = pid >> 4;
        int kl = pid & 15;
        int b = b0 + bl;
        int k = (bx << 4) + kl;
        float gi = gbuf[bl][kl * 4 + 0];
        float gf = gbuf[bl][kl * 4 + 1];
        float gg = gbuf[bl][kl * 4 + 2];
        float go = gbuf[bl][kl * 4 + 3];
        float co = g_c[b * HH + k];
        float cn = fsigmoid(gf) * co + fsigmoid(gi) * ftanh(gg);
        float hn = fsigmoid(go) * ftanh(cn);
        g_c[b * HH + k] = cn;
        Anext[b * KDIM + NN + k] = hn;
        out[(b * TT + t) * HH + k] = hn;
    }
}

// ---------------- launch ----------------
extern "C" void kernel_launch(void* const* d_in, const int* in_sizes, int n_in,
                              void* d_out, int out_size) {
    const float* dx   = (const float*)d_in[0];
    const float* Wa1  = (const float*)d_in[1];
    const float* ba1  = (const float*)d_in[2];
    const float* Wa2  = (const float*)d_in[3];
    const float* ba2  = (const float*)d_in[4];
    const float* Wa3  = (const float*)d_in[5];
    const float* ba3  = (const float*)d_in[6];
    const float* Wih  = (const float*)d_in[7];
    const float* Whh  = (const float*)d_in[8];
    const float* bih  = (const float*)d_in[9];
    const float* bhh  = (const float*)d_in[10];
    float* out = (float*)d_out;

    {
        int tot = 2 * BATCH * KDIM + BATCH * HH;
        k_init<<<(tot + 255) / 256, 256>>>();
    }
    k_prep_w<<<(KDIM * GDIM + 255) / 256, 256>>>(Wih, Whh, bih, bhh);
    k_z2<<<BATCH, 128>>>(dx, Wa2, ba2);

    for (int t = 0; t < TT; t++) {
        int cur = t & 1;
        k_attn<<<BATCH / 2, 256>>>(dx, Wa1, ba1, Wa3, ba3, t, cur);
        k_lstm<<<dim3(GDIM / 64, BATCH / 64), 256>>>(out, t, cur);
    }
}